// round 5
// baseline (speedup 1.0000x reference)
#include <cuda_runtime.h>
#include <cuda_bf16.h>
#include <math.h>

// ---------------------------------------------------------------------------
// Problem constants
// ---------------------------------------------------------------------------
static constexpr int B_    = 32;
static constexpr int C_    = 256;
static constexpr int WS_   = 7;
static constexpr int NH    = 8;
static constexpr int NW    = 64;
static constexpr int NWIN  = B_ * NW;       // 2048
static constexpr int NTOK  = WS_ * WS_ + 1; // 50
static constexpr int MBIG  = NWIN * NTOK;   // 102400
static constexpr int HID   = 4 * C_;        // 1024

// ---------------------------------------------------------------------------
// Scratch
// ---------------------------------------------------------------------------
__device__ float g_X   [(size_t)MBIG * C_];   // window tokens (residual stage C)
__device__ float g_ATT [(size_t)MBIG * C_];   // attention output
__device__ float g_TMP [(size_t)MBIG * C_];   // post-attn state (residual stage D)
__device__ float g_BIG [(size_t)MBIG * HID];  // QKV then H1
__device__ float g_MU  [MBIG];
__device__ float g_RS  [MBIG];

__device__ float g_cflat[(size_t)NWIN * C_];
__device__ float g_cqkv [(size_t)NWIN * 3 * C_];
__device__ float g_catt [(size_t)NWIN * C_];
__device__ float g_c2   [(size_t)NWIN * C_];
__device__ float g_cmu  [NWIN];
__device__ float g_crs  [NWIN];

// ---------------------------------------------------------------------------
// LN stats: one warp per row (C=256). Writes mean and rsqrt(var+eps).
// ---------------------------------------------------------------------------
__global__ void ln_stats(const float* __restrict__ X,
                         float* __restrict__ mu, float* __restrict__ rs, int M)
{
    int row  = blockIdx.x * 8 + (threadIdx.x >> 5);
    int lane = threadIdx.x & 31;
    if (row >= M) return;
    const float4* p = reinterpret_cast<const float4*>(X + (size_t)row * C_);
    float4 v1 = p[lane], v2 = p[lane + 32];
    float s  = v1.x + v1.y + v1.z + v1.w + v2.x + v2.y + v2.z + v2.w;
    float s2 = v1.x*v1.x + v1.y*v1.y + v1.z*v1.z + v1.w*v1.w
             + v2.x*v2.x + v2.y*v2.y + v2.z*v2.z + v2.w*v2.w;
    #pragma unroll
    for (int o = 16; o > 0; o >>= 1) {
        s  += __shfl_xor_sync(0xffffffffu, s,  o);
        s2 += __shfl_xor_sync(0xffffffffu, s2, o);
    }
    if (lane == 0) {
        float m   = s * (1.0f / C_);
        float var = s2 * (1.0f / C_) - m * m;
        mu[row] = m;
        rs[row] = rsqrtf(var + 1e-5f);
    }
}

// ---------------------------------------------------------------------------
// Split-bf16 tensor-core GEMM with optional fused LayerNorm on A and fused
// output scatter. C[M,N] = LN(A)[M,K] @ W[N,K]^T (+bias, +GELU, +residual).
// CTA tile 128x64x32, double-buffered smem, 8 warps (4x2), warp tile 32x32.
// ---------------------------------------------------------------------------
__device__ __forceinline__ void mma16816(float* c, const unsigned* a, const unsigned* b)
{
    asm volatile(
        "mma.sync.aligned.m16n8k16.row.col.f32.bf16.bf16.f32 "
        "{%0,%1,%2,%3},{%4,%5,%6,%7},{%8,%9},{%0,%1,%2,%3};"
        : "+f"(c[0]), "+f"(c[1]), "+f"(c[2]), "+f"(c[3])
        : "r"(a[0]), "r"(a[1]), "r"(a[2]), "r"(a[3]), "r"(b[0]), "r"(b[1]));
}

__device__ __forceinline__ void cvt4(float4 v, unsigned& h01, unsigned& h23,
                                     unsigned& l01, unsigned& l23)
{
    __nv_bfloat16 h0 = __float2bfloat16(v.x);
    __nv_bfloat16 h1 = __float2bfloat16(v.y);
    __nv_bfloat16 h2 = __float2bfloat16(v.z);
    __nv_bfloat16 h3 = __float2bfloat16(v.w);
    __nv_bfloat16 l0 = __float2bfloat16(v.x - __bfloat162float(h0));
    __nv_bfloat16 l1 = __float2bfloat16(v.y - __bfloat162float(h1));
    __nv_bfloat16 l2 = __float2bfloat16(v.z - __bfloat162float(h2));
    __nv_bfloat16 l3 = __float2bfloat16(v.w - __bfloat162float(h3));
    h01 = (unsigned)__bfloat16_as_ushort(h0) | ((unsigned)__bfloat16_as_ushort(h1) << 16);
    h23 = (unsigned)__bfloat16_as_ushort(h2) | ((unsigned)__bfloat16_as_ushort(h3) << 16);
    l01 = (unsigned)__bfloat16_as_ushort(l0) | ((unsigned)__bfloat16_as_ushort(l1) << 16);
    l23 = (unsigned)__bfloat16_as_ushort(l2) | ((unsigned)__bfloat16_as_ushort(l3) << 16);
}

template<int ACT, bool HAS_BIAS, bool HAS_RES, bool LNA, bool SCAT>
__global__ void __launch_bounds__(256)
gemm_tc(const float* __restrict__ A, const float* __restrict__ W,
        const float* __restrict__ bias, const float* __restrict__ res,
        float* __restrict__ Cout, int M, int N, int K,
        const float* __restrict__ mu, const float* __restrict__ rsg,
        const float* __restrict__ lnw, const float* __restrict__ lnb)
{
    constexpr int BM = 128, BN = 64, BK = 32, PAD = 40;
    constexpr int SZA = BM * PAD;              // 5120 shorts
    constexpr int SZB = BN * PAD;              // 2560 shorts
    constexpr int BUFSZ = 2 * SZA + 2 * SZB;   // 15360 shorts per buffer
    extern __shared__ unsigned short smu[];

    const int tid  = threadIdx.x;
    const int wrp  = tid >> 5;
    const int lane = tid & 31;
    const int g    = lane >> 2;
    const int q4   = lane & 3;
    const int wm   = (wrp & 3) * 32;
    const int wn   = (wrp >> 2) * 32;

    const int bm = blockIdx.y * BM;
    const int bn = blockIdx.x * BN;

    float acc[2][4][4];
    #pragma unroll
    for (int i = 0; i < 2; i++)
        #pragma unroll
        for (int j = 0; j < 4; j++)
            #pragma unroll
            for (int t = 0; t < 4; t++) acc[i][j][t] = 0.f;

    float4 aReg[4], bReg[2], w4, b4;
    float amu[4], ars[4];
    const int KT = K / BK;
    const int f  = tid & 7;      // constant k-subcolumn for this thread

    auto loadG = [&](int kt) {
        const float* Abase = A + (size_t)bm * K + kt * BK;
        #pragma unroll
        for (int i = 0; i < 4; i++) {
            int u = tid + i * 256, r = u >> 3;
            aReg[i] = *reinterpret_cast<const float4*>(Abase + (size_t)r * K + f * 4);
            if (LNA) { amu[i] = mu[bm + r]; ars[i] = rsg[bm + r]; }
        }
        if (LNA) {
            w4 = *reinterpret_cast<const float4*>(lnw + kt * BK + f * 4);
            b4 = *reinterpret_cast<const float4*>(lnb + kt * BK + f * 4);
        }
        const float* Wbase = W + (size_t)bn * K + kt * BK;
        #pragma unroll
        for (int i = 0; i < 2; i++) {
            int u = tid + i * 256, r = u >> 3;
            bReg[i] = *reinterpret_cast<const float4*>(Wbase + (size_t)r * K + f * 4);
        }
    };

    auto stS = [&](int buf) {
        unsigned short* Ah = smu + buf * BUFSZ;
        unsigned short* Al = Ah + SZA;
        unsigned short* Bh = Al + SZA;
        unsigned short* Bl = Bh + SZB;
        #pragma unroll
        for (int i = 0; i < 4; i++) {
            int u = tid + i * 256, r = u >> 3;
            float4 v = aReg[i];
            if (LNA) {
                float sc = ars[i];
                v.x = (v.x - amu[i]) * sc * w4.x + b4.x;
                v.y = (v.y - amu[i]) * sc * w4.y + b4.y;
                v.z = (v.z - amu[i]) * sc * w4.z + b4.z;
                v.w = (v.w - amu[i]) * sc * w4.w + b4.w;
            }
            unsigned h01, h23, l01, l23;
            cvt4(v, h01, h23, l01, l23);
            *reinterpret_cast<uint2*>(&Ah[r * PAD + f * 4]) = make_uint2(h01, h23);
            *reinterpret_cast<uint2*>(&Al[r * PAD + f * 4]) = make_uint2(l01, l23);
        }
        #pragma unroll
        for (int i = 0; i < 2; i++) {
            int u = tid + i * 256, r = u >> 3;
            unsigned h01, h23, l01, l23;
            cvt4(bReg[i], h01, h23, l01, l23);
            *reinterpret_cast<uint2*>(&Bh[r * PAD + f * 4]) = make_uint2(h01, h23);
            *reinterpret_cast<uint2*>(&Bl[r * PAD + f * 4]) = make_uint2(l01, l23);
        }
    };

    loadG(0);
    stS(0);
    __syncthreads();

    int buf = 0;
    for (int kt = 0; kt < KT; kt++) {
        if (kt + 1 < KT) loadG(kt + 1);

        unsigned short* Ah = smu + buf * BUFSZ;
        unsigned short* Al = Ah + SZA;
        unsigned short* Bh = Al + SZA;
        unsigned short* Bl = Bh + SZB;

        #pragma unroll
        for (int kk = 0; kk < 2; kk++) {
            const int k0 = kk * 16;
            const int c  = k0 + q4 * 2;
            unsigned a_h[2][4], a_l[2][4], b_h[4][2], b_l[4][2];
            #pragma unroll
            for (int mt = 0; mt < 2; mt++) {
                int r = wm + mt * 16 + g;
                a_h[mt][0] = *reinterpret_cast<unsigned*>(&Ah[r * PAD + c]);
                a_h[mt][1] = *reinterpret_cast<unsigned*>(&Ah[(r + 8) * PAD + c]);
                a_h[mt][2] = *reinterpret_cast<unsigned*>(&Ah[r * PAD + c + 8]);
                a_h[mt][3] = *reinterpret_cast<unsigned*>(&Ah[(r + 8) * PAD + c + 8]);
                a_l[mt][0] = *reinterpret_cast<unsigned*>(&Al[r * PAD + c]);
                a_l[mt][1] = *reinterpret_cast<unsigned*>(&Al[(r + 8) * PAD + c]);
                a_l[mt][2] = *reinterpret_cast<unsigned*>(&Al[r * PAD + c + 8]);
                a_l[mt][3] = *reinterpret_cast<unsigned*>(&Al[(r + 8) * PAD + c + 8]);
            }
            #pragma unroll
            for (int nt = 0; nt < 4; nt++) {
                int n = wn + nt * 8 + g;
                b_h[nt][0] = *reinterpret_cast<unsigned*>(&Bh[n * PAD + c]);
                b_h[nt][1] = *reinterpret_cast<unsigned*>(&Bh[n * PAD + c + 8]);
                b_l[nt][0] = *reinterpret_cast<unsigned*>(&Bl[n * PAD + c]);
                b_l[nt][1] = *reinterpret_cast<unsigned*>(&Bl[n * PAD + c + 8]);
            }
            #pragma unroll
            for (int mt = 0; mt < 2; mt++)
                #pragma unroll
                for (int nt = 0; nt < 4; nt++) {
                    mma16816(acc[mt][nt], a_h[mt], b_h[nt]);
                    mma16816(acc[mt][nt], a_h[mt], b_l[nt]);
                    mma16816(acc[mt][nt], a_l[mt], b_h[nt]);
                }
        }

        if (kt + 1 < KT) {
            stS(buf ^ 1);
            __syncthreads();
        }
        buf ^= 1;
    }

    // Epilogue
    #pragma unroll
    for (int mt = 0; mt < 2; mt++) {
        #pragma unroll
        for (int nt = 0; nt < 4; nt++) {
            int row0 = bm + wm + mt * 16 + g;
            int col0 = bn + wn + nt * 8 + q4 * 2;
            #pragma unroll
            for (int t = 0; t < 4; t++) {
                int row = row0 + (t >> 1) * 8;
                int col = col0 + (t & 1);
                float v = acc[mt][nt][t];
                if (HAS_BIAS) v += bias[col];
                if (ACT == 1) v = 0.5f * v * (1.0f + erff(v * 0.70710678118654752f));
                if (HAS_RES)  v += res[(size_t)row * N + col];
                if (SCAT) {
                    int tt = row % NTOK, w = row / NTOK;
                    int b = w >> 6, wi = w & 63;
                    int hk = wi >> 3, wkx = wi & 7;
                    size_t o;
                    if (tt == 0) {
                        o = (((size_t)b * C_ + col) * 8 + hk) * 8 + wkx;
                    } else {
                        int k = tt - 1, ii = k / 7, jj = k % 7;
                        o = (size_t)B_ * C_ * 64 +
                            (((size_t)b * C_ + col) * 56 + hk * 7 + ii) * 56 + wkx * 7 + jj;
                    }
                    Cout[o] = v;
                } else {
                    Cout[(size_t)row * N + col] = v;
                }
            }
        }
    }
}

// ---------------------------------------------------------------------------
// Attention: one block per (window, head). NT tokens, head dim 32.
// ---------------------------------------------------------------------------
template<int NT, bool BIAS>
__global__ void __launch_bounds__(64)
attn_kernel(const float* __restrict__ QKV,
            const float* __restrict__ rel_pos,
            float* __restrict__ OUT)
{
    int bh = blockIdx.x;
    int w  = bh >> 3;
    int h  = bh & 7;

    __shared__ float qs[NT][32], ks[NT][32], vs[NT][32];
    __shared__ float sc[NT][NT + 3];

    int tid = threadIdx.x;
    const float* base = QKV + (size_t)w * NT * 768 + h * 32;
    for (int idx = tid; idx < NT * 8; idx += 64) {
        int n = idx >> 3, d4 = idx & 7;
        const float4* r = reinterpret_cast<const float4*>(base + (size_t)n * 768 + d4 * 4);
        *reinterpret_cast<float4*>(&qs[n][d4 * 4]) = r[0];
        *reinterpret_cast<float4*>(&ks[n][d4 * 4]) = r[64];   // +256 floats
        *reinterpret_cast<float4*>(&vs[n][d4 * 4]) = r[128];  // +512 floats
    }
    __syncthreads();

    if (tid < NT) {
        int n = tid;
        float q[32];
        #pragma unroll
        for (int d = 0; d < 32; d++) q[d] = qs[n][d];

        const float scale = 0.17677669529663687f;
        float mx = -1e30f;
        for (int m = 0; m < NT; m++) {
            float s = 0.f;
            #pragma unroll
            for (int d = 0; d < 32; d++) s = fmaf(q[d], ks[m][d], s);
            s *= scale;
            if (BIAS) {
                if (n > 0 && m > 0) {
                    int p = n - 1, qq = m - 1;
                    int ridx = ((p / 7) - (qq / 7) + 6) * 13 + ((p % 7) - (qq % 7) + 6);
                    s += rel_pos[h * 225 + ridx];
                }
            }
            sc[n][m] = s;
            mx = fmaxf(mx, s);
        }
        float sum = 0.f;
        for (int m = 0; m < NT; m++) {
            float e = expf(sc[n][m] - mx);
            sc[n][m] = e;
            sum += e;
        }
        float inv = 1.0f / sum;
        float o[32];
        #pragma unroll
        for (int d = 0; d < 32; d++) o[d] = 0.f;
        for (int m = 0; m < NT; m++) {
            float p = sc[n][m];
            #pragma unroll
            for (int d = 0; d < 32; d++) o[d] = fmaf(p, vs[m][d], o[d]);
        }
        float* orow = OUT + (size_t)(w * NT + n) * C_ + h * 32;
        #pragma unroll
        for (int d = 0; d < 32; d++) orow[d] = o[d] * inv;
    }
}

// ---------------------------------------------------------------------------
// Data movement
// ---------------------------------------------------------------------------
__global__ void k_gather_cls(const float* __restrict__ cls)
{
    int idx = blockIdx.x * blockDim.x + threadIdx.x;
    if (idx >= NWIN * C_) return;
    int c = idx & 255, row = idx >> 8;
    int b = row >> 6, n = row & 63;
    g_cflat[idx] = cls[((size_t)b * C_ + c) * 64 + n];
}

__global__ void k_buildX(const float* __restrict__ patch)
{
    int idx = blockIdx.x * blockDim.x + threadIdx.x;
    if (idx >= MBIG * C_) return;
    int c = idx & 255, row = idx >> 8;
    int t = row % NTOK, w = row / NTOK;
    if (t == 0) {
        g_X[idx] = g_c2[(size_t)w * C_ + c];
    } else {
        int b = w >> 6, wi = w & 63;
        int hk = wi >> 3, wkx = wi & 7;
        int k = t - 1, i = k / 7, j = k % 7;
        g_X[idx] = patch[(((size_t)b * C_ + c) * 56 + hk * 7 + i) * 56 + wkx * 7 + j];
    }
}

// ---------------------------------------------------------------------------
// Host launcher
// ---------------------------------------------------------------------------
extern "C" void kernel_launch(void* const* d_in, const int* in_sizes, int n_in,
                              void* d_out, int out_size)
{
    (void)in_sizes; (void)n_in; (void)out_size;
    const float* cls_tokens   = (const float*)d_in[0];
    const float* patch_tokens = (const float*)d_in[1];
    const float* n0w = (const float*)d_in[2];
    const float* n0b = (const float*)d_in[3];
    const float* n1w = (const float*)d_in[4];
    const float* n1b = (const float*)d_in[5];
    const float* n2w = (const float*)d_in[6];
    const float* n2b = (const float*)d_in[7];
    const float* qkv_w  = (const float*)d_in[8];
    const float* proj_w = (const float*)d_in[9];
    const float* proj_b = (const float*)d_in[10];
    const float* rel_pos= (const float*)d_in[11];
    const float* fc1_w  = (const float*)d_in[12];
    const float* fc1_b  = (const float*)d_in[13];
    const float* fc2_w  = (const float*)d_in[14];
    const float* fc2_b  = (const float*)d_in[15];
    float* out = (float*)d_out;

    static float *X = nullptr, *ATT = nullptr, *TMP = nullptr, *BIG = nullptr;
    static float *MU = nullptr, *RS = nullptr;
    static float *cf = nullptr, *cq = nullptr, *ca = nullptr, *c2 = nullptr;
    static float *cmu = nullptr, *crs = nullptr;
    if (!X) {
        cudaGetSymbolAddress((void**)&X,   g_X);
        cudaGetSymbolAddress((void**)&ATT, g_ATT);
        cudaGetSymbolAddress((void**)&TMP, g_TMP);
        cudaGetSymbolAddress((void**)&BIG, g_BIG);
        cudaGetSymbolAddress((void**)&MU,  g_MU);
        cudaGetSymbolAddress((void**)&RS,  g_RS);
        cudaGetSymbolAddress((void**)&cf,  g_cflat);
        cudaGetSymbolAddress((void**)&cq,  g_cqkv);
        cudaGetSymbolAddress((void**)&ca,  g_catt);
        cudaGetSymbolAddress((void**)&c2,  g_c2);
        cudaGetSymbolAddress((void**)&cmu, g_cmu);
        cudaGetSymbolAddress((void**)&crs, g_crs);
        const int smem = 61440;
        cudaFuncSetAttribute(gemm_tc<0, false, false, true, false>,
                             cudaFuncAttributeMaxDynamicSharedMemorySize, smem);
        cudaFuncSetAttribute(gemm_tc<0, true, true, false, false>,
                             cudaFuncAttributeMaxDynamicSharedMemorySize, smem);
        cudaFuncSetAttribute(gemm_tc<1, true, false, true, false>,
                             cudaFuncAttributeMaxDynamicSharedMemorySize, smem);
        cudaFuncSetAttribute(gemm_tc<0, true, true, false, true>,
                             cudaFuncAttributeMaxDynamicSharedMemorySize, smem);
    }

    const int TPB  = 256;
    const int SMEM = 61440;

    // ---- Stage A: cls MHA ----
    k_gather_cls<<<(NWIN * C_ + TPB - 1) / TPB, TPB>>>(cls_tokens);
    ln_stats<<<NWIN / 8, 256>>>(cf, cmu, crs, NWIN);
    gemm_tc<0, false, false, true, false><<<dim3(3 * C_ / 64, NWIN / 128), 256, SMEM>>>(
        cf, qkv_w, nullptr, nullptr, cq, NWIN, 3 * C_, C_, cmu, crs, n0w, n0b);
    attn_kernel<64, false><<<B_ * NH, 64>>>(cq, nullptr, ca);
    gemm_tc<0, true, true, false, false><<<dim3(C_ / 64, NWIN / 128), 256, SMEM>>>(
        ca, proj_w, proj_b, cf, c2, NWIN, C_, C_, nullptr, nullptr, nullptr, nullptr);

    // ---- Stage B: build X ----
    k_buildX<<<(MBIG * C_ + TPB - 1) / TPB, TPB>>>(patch_tokens);

    // ---- Stage C: windowed MHA + rel bias ----
    ln_stats<<<MBIG / 8, 256>>>(X, MU, RS, MBIG);
    gemm_tc<0, false, false, true, false><<<dim3(3 * C_ / 64, MBIG / 128), 256, SMEM>>>(
        X, qkv_w, nullptr, nullptr, BIG, MBIG, 3 * C_, C_, MU, RS, n1w, n1b);
    attn_kernel<50, true><<<NWIN * NH, 64>>>(BIG, rel_pos, ATT);
    gemm_tc<0, true, true, false, false><<<dim3(C_ / 64, MBIG / 128), 256, SMEM>>>(
        ATT, proj_w, proj_b, X, TMP, MBIG, C_, C_, nullptr, nullptr, nullptr, nullptr);

    // ---- Stage D: MLP (LN fused into fc1; scatter fused into fc2) ----
    ln_stats<<<MBIG / 8, 256>>>(TMP, MU, RS, MBIG);
    gemm_tc<1, true, false, true, false><<<dim3(HID / 64, MBIG / 128), 256, SMEM>>>(
        TMP, fc1_w, fc1_b, nullptr, BIG, MBIG, HID, C_, MU, RS, n2w, n2b);
    gemm_tc<0, true, true, false, true><<<dim3(C_ / 64, MBIG / 128), 256, SMEM>>>(
        BIG, fc2_w, fc2_b, TMP, out, MBIG, C_, HID, nullptr, nullptr, nullptr, nullptr);
}

// round 6
// speedup vs baseline: 1.1109x; 1.1109x over previous
#include <cuda_runtime.h>
#include <cuda_bf16.h>
#include <math.h>

// ---------------------------------------------------------------------------
// Problem constants
// ---------------------------------------------------------------------------
static constexpr int B_    = 32;
static constexpr int C_    = 256;
static constexpr int WS_   = 7;
static constexpr int NH    = 8;
static constexpr int NW    = 64;
static constexpr int NWIN  = B_ * NW;       // 2048
static constexpr int NTOK  = WS_ * WS_ + 1; // 50
static constexpr int MBIG  = NWIN * NTOK;   // 102400
static constexpr int HID   = 4 * C_;        // 1024

// ---------------------------------------------------------------------------
// Scratch
// ---------------------------------------------------------------------------
__device__ float g_X   [(size_t)MBIG * C_];      // window tokens (residual C)
__device__ float g_TMP [(size_t)MBIG * C_];      // post-attn state (residual D)
__device__ float g_QKV [(size_t)MBIG * 3 * C_];  // qkv fp32 (attention input)
__device__ float g_MU  [MBIG];
__device__ float g_RS  [MBIG];

// split-bf16 activation buffers
__device__ __nv_bfloat16 g_LNh [(size_t)MBIG * C_];   // LN(X) / LN(TMP) hi (reused)
__device__ __nv_bfloat16 g_LNl [(size_t)MBIG * C_];
__device__ __nv_bfloat16 g_ATh [(size_t)MBIG * C_];   // attention out hi
__device__ __nv_bfloat16 g_ATl [(size_t)MBIG * C_];
__device__ __nv_bfloat16 g_H1h [(size_t)MBIG * HID];  // MLP hidden hi
__device__ __nv_bfloat16 g_H1l [(size_t)MBIG * HID];

// split-bf16 weights
__device__ __nv_bfloat16 g_Wqh[3 * C_ * C_], g_Wql[3 * C_ * C_];
__device__ __nv_bfloat16 g_Wph[C_ * C_],     g_Wpl[C_ * C_];
__device__ __nv_bfloat16 g_W1h[HID * C_],    g_W1l[HID * C_];
__device__ __nv_bfloat16 g_W2h[C_ * HID],    g_W2l[C_ * HID];

// cls path scratch (fp32, old kernels)
__device__ float g_cflat[(size_t)NWIN * C_];
__device__ float g_cqkv [(size_t)NWIN * 3 * C_];
__device__ float g_catt [(size_t)NWIN * C_];
__device__ float g_c2   [(size_t)NWIN * C_];
__device__ float g_cmu  [NWIN];
__device__ float g_crs  [NWIN];

// ---------------------------------------------------------------------------
// Helpers
// ---------------------------------------------------------------------------
__device__ __forceinline__ void mma16816(float* c, const unsigned* a, const unsigned* b)
{
    asm volatile(
        "mma.sync.aligned.m16n8k16.row.col.f32.bf16.bf16.f32 "
        "{%0,%1,%2,%3},{%4,%5,%6,%7},{%8,%9},{%0,%1,%2,%3};"
        : "+f"(c[0]), "+f"(c[1]), "+f"(c[2]), "+f"(c[3])
        : "r"(a[0]), "r"(a[1]), "r"(a[2]), "r"(a[3]), "r"(b[0]), "r"(b[1]));
}

__device__ __forceinline__ void cpa8(void* dst, const void* src)
{
    unsigned d = (unsigned)__cvta_generic_to_shared(dst);
    asm volatile("cp.async.ca.shared.global [%0], [%1], 8;" :: "r"(d), "l"(src));
}
__device__ __forceinline__ void cpa_commit() { asm volatile("cp.async.commit_group;"); }

__device__ __forceinline__ void split2(float v, __nv_bfloat16& h, __nv_bfloat16& l)
{
    h = __float2bfloat16(v);
    l = __float2bfloat16(v - __bfloat162float(h));
}

// ---------------------------------------------------------------------------
// LN stats: one warp per row (C=256)
// ---------------------------------------------------------------------------
__global__ void ln_stats(const float* __restrict__ X,
                         float* __restrict__ mu, float* __restrict__ rs, int M)
{
    int row  = blockIdx.x * 8 + (threadIdx.x >> 5);
    int lane = threadIdx.x & 31;
    if (row >= M) return;
    const float4* p = reinterpret_cast<const float4*>(X + (size_t)row * C_);
    float4 v1 = p[lane], v2 = p[lane + 32];
    float s  = v1.x + v1.y + v1.z + v1.w + v2.x + v2.y + v2.z + v2.w;
    float s2 = v1.x*v1.x + v1.y*v1.y + v1.z*v1.z + v1.w*v1.w
             + v2.x*v2.x + v2.y*v2.y + v2.z*v2.z + v2.w*v2.w;
    #pragma unroll
    for (int o = 16; o > 0; o >>= 1) {
        s  += __shfl_xor_sync(0xffffffffu, s,  o);
        s2 += __shfl_xor_sync(0xffffffffu, s2, o);
    }
    if (lane == 0) {
        float m   = s * (1.0f / C_);
        float var = s2 * (1.0f / C_) - m * m;
        mu[row] = m;
        rs[row] = rsqrtf(var + 1e-5f);
    }
}

// LN + split to bf16 hi/lo. 4 elements per thread.
__global__ void k_ln2bf(const float* __restrict__ X,
                        const float* __restrict__ mu, const float* __restrict__ rs,
                        const float* __restrict__ w, const float* __restrict__ b,
                        __nv_bfloat16* __restrict__ hi, __nv_bfloat16* __restrict__ lo)
{
    int idx = blockIdx.x * blockDim.x + threadIdx.x;   // over MBIG*C/4
    int row = idx >> 6, c = (idx & 63) * 4;
    float4 x  = *reinterpret_cast<const float4*>(X + (size_t)row * C_ + c);
    float4 w4 = *reinterpret_cast<const float4*>(w + c);
    float4 b4 = *reinterpret_cast<const float4*>(b + c);
    float m = mu[row], r = rs[row];
    float y0 = (x.x - m) * r * w4.x + b4.x;
    float y1 = (x.y - m) * r * w4.y + b4.y;
    float y2 = (x.z - m) * r * w4.z + b4.z;
    float y3 = (x.w - m) * r * w4.w + b4.w;
    __nv_bfloat16 h0, h1, h2, h3, l0, l1, l2, l3;
    split2(y0, h0, l0); split2(y1, h1, l1); split2(y2, h2, l2); split2(y3, h3, l3);
    size_t o = (size_t)row * C_ + c;
    *reinterpret_cast<__nv_bfloat162*>(hi + o)     = __nv_bfloat162(h0, h1);
    *reinterpret_cast<__nv_bfloat162*>(hi + o + 2) = __nv_bfloat162(h2, h3);
    *reinterpret_cast<__nv_bfloat162*>(lo + o)     = __nv_bfloat162(l0, l1);
    *reinterpret_cast<__nv_bfloat162*>(lo + o + 2) = __nv_bfloat162(l2, l3);
}

// weight split
__global__ void k_split(const float* __restrict__ src,
                        __nv_bfloat16* __restrict__ hi, __nv_bfloat16* __restrict__ lo, int n)
{
    int idx = blockIdx.x * blockDim.x + threadIdx.x;
    if (idx >= n) return;
    __nv_bfloat16 h, l;
    split2(src[idx], h, l);
    hi[idx] = h; lo[idx] = l;
}

// ---------------------------------------------------------------------------
// Split-bf16 GEMM v2: pure cp.async + LDS + MMA (no in-loop conversion).
// C[M,N] = (Ahi+Alo)[M,K] @ (Whi+Wlo)[N,K]^T, 3-term: AhBh + AhBl + AlBh.
// CTA tile 128x64x32, 2-stage cp.async pipeline, 8 warps 4x2, warp tile 32x32.
// OUTM: 0 = fp32, 1 = bf16 hi/lo, 2 = fp32 scatter to output layout.
// ---------------------------------------------------------------------------
template<int ACT, bool HAS_BIAS, bool HAS_RES, int OUTM>
__global__ void __launch_bounds__(256)
gemm_bf(const __nv_bfloat16* __restrict__ Ahi, const __nv_bfloat16* __restrict__ Alo,
        const __nv_bfloat16* __restrict__ Whi, const __nv_bfloat16* __restrict__ Wlo,
        const float* __restrict__ bias, const float* __restrict__ res,
        float* __restrict__ Cout,
        __nv_bfloat16* __restrict__ Ohi, __nv_bfloat16* __restrict__ Olo,
        int M, int N, int K)
{
    constexpr int BM = 128, BN = 64, BK = 32, PAD = 40;
    constexpr int SZA = BM * PAD;              // shorts
    constexpr int SZB = BN * PAD;
    constexpr int BUFSZ = 2 * SZA + 2 * SZB;   // 15360 shorts = 30720 B
    extern __shared__ unsigned short smu[];

    const int tid  = threadIdx.x;
    const int wrp  = tid >> 5;
    const int lane = tid & 31;
    const int g    = lane >> 2;
    const int q4   = lane & 3;
    const int wm   = (wrp & 3) * 32;
    const int wn   = (wrp >> 2) * 32;
    const int bm   = blockIdx.y * BM;
    const int bn   = blockIdx.x * BN;

    const int r8 = tid >> 3;     // 0..31 row group base for fills
    const int f  = tid & 7;      // 8-byte chunk within 64B row

    float acc[2][4][4];
    #pragma unroll
    for (int i = 0; i < 2; i++)
        #pragma unroll
        for (int j = 0; j < 4; j++)
            #pragma unroll
            for (int t = 0; t < 4; t++) acc[i][j][t] = 0.f;

    const int KT = K / BK;

    auto fill = [&](int buf, int kt) {
        unsigned short* Ah = smu + buf * BUFSZ;
        unsigned short* Al = Ah + SZA;
        unsigned short* Bh = Al + SZA;
        unsigned short* Bl = Bh + SZB;
        const size_t koff = (size_t)kt * BK;
        #pragma unroll
        for (int i = 0; i < 4; i++) {
            int r = r8 + i * 32;
            const size_t go = (size_t)(bm + r) * K + koff + f * 4;
            cpa8(&Ah[r * PAD + f * 4], Ahi + go);
            cpa8(&Al[r * PAD + f * 4], Alo + go);
        }
        #pragma unroll
        for (int i = 0; i < 2; i++) {
            int r = r8 + i * 32;
            const size_t go = (size_t)(bn + r) * K + koff + f * 4;
            cpa8(&Bh[r * PAD + f * 4], Whi + go);
            cpa8(&Bl[r * PAD + f * 4], Wlo + go);
        }
    };

    fill(0, 0);
    cpa_commit();

    int buf = 0;
    for (int kt = 0; kt < KT; kt++) {
        if (kt + 1 < KT) {
            fill(buf ^ 1, kt + 1);
            cpa_commit();
            asm volatile("cp.async.wait_group 1;");
        } else {
            asm volatile("cp.async.wait_group 0;");
        }
        __syncthreads();

        unsigned short* Ah = smu + buf * BUFSZ;
        unsigned short* Al = Ah + SZA;
        unsigned short* Bh = Al + SZA;
        unsigned short* Bl = Bh + SZB;

        #pragma unroll
        for (int kk = 0; kk < 2; kk++) {
            const int c = kk * 16 + q4 * 2;
            unsigned a_h[2][4], a_l[2][4], b_h[4][2], b_l[4][2];
            #pragma unroll
            for (int mt = 0; mt < 2; mt++) {
                int r = wm + mt * 16 + g;
                a_h[mt][0] = *reinterpret_cast<unsigned*>(&Ah[r * PAD + c]);
                a_h[mt][1] = *reinterpret_cast<unsigned*>(&Ah[(r + 8) * PAD + c]);
                a_h[mt][2] = *reinterpret_cast<unsigned*>(&Ah[r * PAD + c + 8]);
                a_h[mt][3] = *reinterpret_cast<unsigned*>(&Ah[(r + 8) * PAD + c + 8]);
                a_l[mt][0] = *reinterpret_cast<unsigned*>(&Al[r * PAD + c]);
                a_l[mt][1] = *reinterpret_cast<unsigned*>(&Al[(r + 8) * PAD + c]);
                a_l[mt][2] = *reinterpret_cast<unsigned*>(&Al[r * PAD + c + 8]);
                a_l[mt][3] = *reinterpret_cast<unsigned*>(&Al[(r + 8) * PAD + c + 8]);
            }
            #pragma unroll
            for (int nt = 0; nt < 4; nt++) {
                int n = wn + nt * 8 + g;
                b_h[nt][0] = *reinterpret_cast<unsigned*>(&Bh[n * PAD + c]);
                b_h[nt][1] = *reinterpret_cast<unsigned*>(&Bh[n * PAD + c + 8]);
                b_l[nt][0] = *reinterpret_cast<unsigned*>(&Bl[n * PAD + c]);
                b_l[nt][1] = *reinterpret_cast<unsigned*>(&Bl[n * PAD + c + 8]);
            }
            #pragma unroll
            for (int mt = 0; mt < 2; mt++)
                #pragma unroll
                for (int nt = 0; nt < 4; nt++) {
                    mma16816(acc[mt][nt], a_h[mt], b_h[nt]);
                    mma16816(acc[mt][nt], a_h[mt], b_l[nt]);
                    mma16816(acc[mt][nt], a_l[mt], b_h[nt]);
                }
        }
        __syncthreads();
        buf ^= 1;
    }

    // Epilogue
    #pragma unroll
    for (int mt = 0; mt < 2; mt++) {
        #pragma unroll
        for (int nt = 0; nt < 4; nt++) {
            int row0 = bm + wm + mt * 16 + g;
            int col0 = bn + wn + nt * 8 + q4 * 2;
            #pragma unroll
            for (int tp = 0; tp < 2; tp++) {
                int row = row0 + tp * 8;
                float v0 = acc[mt][nt][tp * 2 + 0];
                float v1 = acc[mt][nt][tp * 2 + 1];
                if (HAS_BIAS) { v0 += bias[col0]; v1 += bias[col0 + 1]; }
                if (ACT == 1) {
                    v0 = 0.5f * v0 * (1.0f + erff(v0 * 0.70710678118654752f));
                    v1 = 0.5f * v1 * (1.0f + erff(v1 * 0.70710678118654752f));
                }
                if (HAS_RES) {
                    float2 rr = *reinterpret_cast<const float2*>(res + (size_t)row * N + col0);
                    v0 += rr.x; v1 += rr.y;
                }
                if (OUTM == 0) {
                    *reinterpret_cast<float2*>(Cout + (size_t)row * N + col0) =
                        make_float2(v0, v1);
                } else if (OUTM == 1) {
                    __nv_bfloat16 h0, h1, l0, l1;
                    split2(v0, h0, l0); split2(v1, h1, l1);
                    size_t o = (size_t)row * N + col0;
                    *reinterpret_cast<__nv_bfloat162*>(Ohi + o) = __nv_bfloat162(h0, h1);
                    *reinterpret_cast<__nv_bfloat162*>(Olo + o) = __nv_bfloat162(l0, l1);
                } else {
                    int tt = row % NTOK, w = row / NTOK;
                    int b = w >> 6, wi = w & 63;
                    int hk = wi >> 3, wkx = wi & 7;
                    #pragma unroll
                    for (int e = 0; e < 2; e++) {
                        int col = col0 + e;
                        float v = (e == 0) ? v0 : v1;
                        size_t o;
                        if (tt == 0) {
                            o = (((size_t)b * C_ + col) * 8 + hk) * 8 + wkx;
                        } else {
                            int k = tt - 1, ii = k / 7, jj = k % 7;
                            o = (size_t)B_ * C_ * 64 +
                                (((size_t)b * C_ + col) * 56 + hk * 7 + ii) * 56 + wkx * 7 + jj;
                        }
                        Cout[o] = v;
                    }
                }
            }
        }
    }
}

// ---------------------------------------------------------------------------
// Old fp32->split GEMM (cls path only; proven correct)
// ---------------------------------------------------------------------------
__device__ __forceinline__ void cvt4(float4 v, unsigned& h01, unsigned& h23,
                                     unsigned& l01, unsigned& l23)
{
    __nv_bfloat16 h0 = __float2bfloat16(v.x);
    __nv_bfloat16 h1 = __float2bfloat16(v.y);
    __nv_bfloat16 h2 = __float2bfloat16(v.z);
    __nv_bfloat16 h3 = __float2bfloat16(v.w);
    __nv_bfloat16 l0 = __float2bfloat16(v.x - __bfloat162float(h0));
    __nv_bfloat16 l1 = __float2bfloat16(v.y - __bfloat162float(h1));
    __nv_bfloat16 l2 = __float2bfloat16(v.z - __bfloat162float(h2));
    __nv_bfloat16 l3 = __float2bfloat16(v.w - __bfloat162float(h3));
    h01 = (unsigned)__bfloat16_as_ushort(h0) | ((unsigned)__bfloat16_as_ushort(h1) << 16);
    h23 = (unsigned)__bfloat16_as_ushort(h2) | ((unsigned)__bfloat16_as_ushort(h3) << 16);
    l01 = (unsigned)__bfloat16_as_ushort(l0) | ((unsigned)__bfloat16_as_ushort(l1) << 16);
    l23 = (unsigned)__bfloat16_as_ushort(l2) | ((unsigned)__bfloat16_as_ushort(l3) << 16);
}

template<bool HAS_BIAS, bool HAS_RES, bool LNA>
__global__ void __launch_bounds__(256)
gemm_tc(const float* __restrict__ A, const float* __restrict__ W,
        const float* __restrict__ bias, const float* __restrict__ res,
        float* __restrict__ Cout, int M, int N, int K,
        const float* __restrict__ mu, const float* __restrict__ rsg,
        const float* __restrict__ lnw, const float* __restrict__ lnb)
{
    constexpr int BM = 128, BN = 64, BK = 32, PAD = 40;
    __shared__ __align__(16) unsigned short Ah[BM * PAD], Al[BM * PAD];
    __shared__ __align__(16) unsigned short Bh[BN * PAD], Bl[BN * PAD];

    const int tid  = threadIdx.x;
    const int wrp  = tid >> 5;
    const int lane = tid & 31;
    const int g    = lane >> 2;
    const int q4   = lane & 3;
    const int wm   = (wrp & 3) * 32;
    const int wn   = (wrp >> 2) * 32;
    const int bm = blockIdx.y * BM;
    const int bn = blockIdx.x * BN;

    float acc[2][4][4];
    #pragma unroll
    for (int i = 0; i < 2; i++)
        #pragma unroll
        for (int j = 0; j < 4; j++)
            #pragma unroll
            for (int t = 0; t < 4; t++) acc[i][j][t] = 0.f;

    const int KT = K / BK;
    const int f  = tid & 7;

    for (int kt = 0; kt < KT; kt++) {
        #pragma unroll
        for (int i = 0; i < 4; i++) {
            int u = tid + i * 256, r = u >> 3;
            float4 v = *reinterpret_cast<const float4*>(
                A + (size_t)(bm + r) * K + kt * BK + f * 4);
            if (LNA) {
                float m = mu[bm + r], sc = rsg[bm + r];
                float4 w4 = *reinterpret_cast<const float4*>(lnw + kt * BK + f * 4);
                float4 b4 = *reinterpret_cast<const float4*>(lnb + kt * BK + f * 4);
                v.x = (v.x - m) * sc * w4.x + b4.x;
                v.y = (v.y - m) * sc * w4.y + b4.y;
                v.z = (v.z - m) * sc * w4.z + b4.z;
                v.w = (v.w - m) * sc * w4.w + b4.w;
            }
            unsigned h01, h23, l01, l23;
            cvt4(v, h01, h23, l01, l23);
            *reinterpret_cast<uint2*>(&Ah[r * PAD + f * 4]) = make_uint2(h01, h23);
            *reinterpret_cast<uint2*>(&Al[r * PAD + f * 4]) = make_uint2(l01, l23);
        }
        #pragma unroll
        for (int i = 0; i < 2; i++) {
            int u = tid + i * 256, r = u >> 3;
            float4 v = *reinterpret_cast<const float4*>(
                W + (size_t)(bn + r) * K + kt * BK + f * 4);
            unsigned h01, h23, l01, l23;
            cvt4(v, h01, h23, l01, l23);
            *reinterpret_cast<uint2*>(&Bh[r * PAD + f * 4]) = make_uint2(h01, h23);
            *reinterpret_cast<uint2*>(&Bl[r * PAD + f * 4]) = make_uint2(l01, l23);
        }
        __syncthreads();
        #pragma unroll
        for (int kk = 0; kk < 2; kk++) {
            const int c = kk * 16 + q4 * 2;
            unsigned a_h[2][4], a_l[2][4], b_h[4][2], b_l[4][2];
            #pragma unroll
            for (int mt = 0; mt < 2; mt++) {
                int r = wm + mt * 16 + g;
                a_h[mt][0] = *reinterpret_cast<unsigned*>(&Ah[r * PAD + c]);
                a_h[mt][1] = *reinterpret_cast<unsigned*>(&Ah[(r + 8) * PAD + c]);
                a_h[mt][2] = *reinterpret_cast<unsigned*>(&Ah[r * PAD + c + 8]);
                a_h[mt][3] = *reinterpret_cast<unsigned*>(&Ah[(r + 8) * PAD + c + 8]);
                a_l[mt][0] = *reinterpret_cast<unsigned*>(&Al[r * PAD + c]);
                a_l[mt][1] = *reinterpret_cast<unsigned*>(&Al[(r + 8) * PAD + c]);
                a_l[mt][2] = *reinterpret_cast<unsigned*>(&Al[r * PAD + c + 8]);
                a_l[mt][3] = *reinterpret_cast<unsigned*>(&Al[(r + 8) * PAD + c + 8]);
            }
            #pragma unroll
            for (int nt = 0; nt < 4; nt++) {
                int n = wn + nt * 8 + g;
                b_h[nt][0] = *reinterpret_cast<unsigned*>(&Bh[n * PAD + c]);
                b_h[nt][1] = *reinterpret_cast<unsigned*>(&Bh[n * PAD + c + 8]);
                b_l[nt][0] = *reinterpret_cast<unsigned*>(&Bl[n * PAD + c]);
                b_l[nt][1] = *reinterpret_cast<unsigned*>(&Bl[n * PAD + c + 8]);
            }
            #pragma unroll
            for (int mt = 0; mt < 2; mt++)
                #pragma unroll
                for (int nt = 0; nt < 4; nt++) {
                    mma16816(acc[mt][nt], a_h[mt], b_h[nt]);
                    mma16816(acc[mt][nt], a_h[mt], b_l[nt]);
                    mma16816(acc[mt][nt], a_l[mt], b_h[nt]);
                }
        }
        __syncthreads();
    }

    #pragma unroll
    for (int mt = 0; mt < 2; mt++)
        #pragma unroll
        for (int nt = 0; nt < 4; nt++) {
            int row0 = bm + wm + mt * 16 + g;
            int col0 = bn + wn + nt * 8 + q4 * 2;
            #pragma unroll
            for (int t = 0; t < 4; t++) {
                int row = row0 + (t >> 1) * 8;
                int col = col0 + (t & 1);
                float v = acc[mt][nt][t];
                if (HAS_BIAS) v += bias[col];
                if (HAS_RES)  v += res[(size_t)row * N + col];
                Cout[(size_t)row * N + col] = v;
            }
        }
}

// ---------------------------------------------------------------------------
// Attention: one block per (window, head). NT tokens, head dim 32.
// BFOUT: write hi/lo bf16 instead of fp32.
// ---------------------------------------------------------------------------
template<int NT, bool BIAS, bool BFOUT>
__global__ void __launch_bounds__(64)
attn_kernel(const float* __restrict__ QKV,
            const float* __restrict__ rel_pos,
            float* __restrict__ OUT,
            __nv_bfloat16* __restrict__ Ohi, __nv_bfloat16* __restrict__ Olo)
{
    int bh = blockIdx.x;
    int w  = bh >> 3;
    int h  = bh & 7;

    __shared__ float qs[NT][32], ks[NT][32], vs[NT][32];
    __shared__ float sc[NT][NT + 3];

    int tid = threadIdx.x;
    const float* base = QKV + (size_t)w * NT * 768 + h * 32;
    for (int idx = tid; idx < NT * 8; idx += 64) {
        int n = idx >> 3, d4 = idx & 7;
        const float4* r = reinterpret_cast<const float4*>(base + (size_t)n * 768 + d4 * 4);
        *reinterpret_cast<float4*>(&qs[n][d4 * 4]) = r[0];
        *reinterpret_cast<float4*>(&ks[n][d4 * 4]) = r[64];
        *reinterpret_cast<float4*>(&vs[n][d4 * 4]) = r[128];
    }
    __syncthreads();

    if (tid < NT) {
        int n = tid;
        float q[32];
        #pragma unroll
        for (int d = 0; d < 32; d++) q[d] = qs[n][d];

        const float scale = 0.17677669529663687f;
        float mx = -1e30f;
        for (int m = 0; m < NT; m++) {
            float s = 0.f;
            #pragma unroll
            for (int d = 0; d < 32; d++) s = fmaf(q[d], ks[m][d], s);
            s *= scale;
            if (BIAS) {
                if (n > 0 && m > 0) {
                    int p = n - 1, qq = m - 1;
                    int ridx = ((p / 7) - (qq / 7) + 6) * 13 + ((p % 7) - (qq % 7) + 6);
                    s += rel_pos[h * 225 + ridx];
                }
            }
            sc[n][m] = s;
            mx = fmaxf(mx, s);
        }
        float sum = 0.f;
        for (int m = 0; m < NT; m++) {
            float e = expf(sc[n][m] - mx);
            sc[n][m] = e;
            sum += e;
        }
        float inv = 1.0f / sum;
        float o[32];
        #pragma unroll
        for (int d = 0; d < 32; d++) o[d] = 0.f;
        for (int m = 0; m < NT; m++) {
            float p = sc[n][m];
            #pragma unroll
            for (int d = 0; d < 32; d++) o[d] = fmaf(p, vs[m][d], o[d]);
        }
        size_t rowoff = (size_t)(w * NT + n) * C_ + h * 32;
        if (BFOUT) {
            #pragma unroll
            for (int d = 0; d < 32; d++) {
                float vv = o[d] * inv;
                __nv_bfloat16 hh, ll;
                split2(vv, hh, ll);
                Ohi[rowoff + d] = hh;
                Olo[rowoff + d] = ll;
            }
        } else {
            #pragma unroll
            for (int d = 0; d < 32; d++) OUT[rowoff + d] = o[d] * inv;
        }
    }
}

// ---------------------------------------------------------------------------
// Data movement
// ---------------------------------------------------------------------------
__global__ void k_gather_cls(const float* __restrict__ cls)
{
    int idx = blockIdx.x * blockDim.x + threadIdx.x;
    if (idx >= NWIN * C_) return;
    int c = idx & 255, row = idx >> 8;
    int b = row >> 6, n = row & 63;
    g_cflat[idx] = cls[((size_t)b * C_ + c) * 64 + n];
}

__global__ void k_buildX(const float* __restrict__ patch)
{
    int idx = blockIdx.x * blockDim.x + threadIdx.x;
    if (idx >= MBIG * C_) return;
    int c = idx & 255, row = idx >> 8;
    int t = row % NTOK, w = row / NTOK;
    if (t == 0) {
        g_X[idx] = g_c2[(size_t)w * C_ + c];
    } else {
        int b = w >> 6, wi = w & 63;
        int hk = wi >> 3, wkx = wi & 7;
        int k = t - 1, i = k / 7, j = k % 7;
        g_X[idx] = patch[(((size_t)b * C_ + c) * 56 + hk * 7 + i) * 56 + wkx * 7 + j];
    }
}

// ---------------------------------------------------------------------------
// Host launcher
// ---------------------------------------------------------------------------
extern "C" void kernel_launch(void* const* d_in, const int* in_sizes, int n_in,
                              void* d_out, int out_size)
{
    (void)in_sizes; (void)n_in; (void)out_size;
    const float* cls_tokens   = (const float*)d_in[0];
    const float* patch_tokens = (const float*)d_in[1];
    const float* n0w = (const float*)d_in[2];
    const float* n0b = (const float*)d_in[3];
    const float* n1w = (const float*)d_in[4];
    const float* n1b = (const float*)d_in[5];
    const float* n2w = (const float*)d_in[6];
    const float* n2b = (const float*)d_in[7];
    const float* qkv_w  = (const float*)d_in[8];
    const float* proj_w = (const float*)d_in[9];
    const float* proj_b = (const float*)d_in[10];
    const float* rel_pos= (const float*)d_in[11];
    const float* fc1_w  = (const float*)d_in[12];
    const float* fc1_b  = (const float*)d_in[13];
    const float* fc2_w  = (const float*)d_in[14];
    const float* fc2_b  = (const float*)d_in[15];
    float* out = (float*)d_out;

    static float *X = nullptr, *TMP, *QKV, *MU, *RS;
    static __nv_bfloat16 *LNh, *LNl, *ATh, *ATl, *H1h, *H1l;
    static __nv_bfloat16 *Wqh, *Wql, *Wph, *Wpl, *W1h, *W1l, *W2h, *W2l;
    static float *cf, *cq, *ca, *c2, *cmu, *crs;
    if (!X) {
        cudaGetSymbolAddress((void**)&X,   g_X);
        cudaGetSymbolAddress((void**)&TMP, g_TMP);
        cudaGetSymbolAddress((void**)&QKV, g_QKV);
        cudaGetSymbolAddress((void**)&MU,  g_MU);
        cudaGetSymbolAddress((void**)&RS,  g_RS);
        cudaGetSymbolAddress((void**)&LNh, g_LNh);
        cudaGetSymbolAddress((void**)&LNl, g_LNl);
        cudaGetSymbolAddress((void**)&ATh, g_ATh);
        cudaGetSymbolAddress((void**)&ATl, g_ATl);
        cudaGetSymbolAddress((void**)&H1h, g_H1h);
        cudaGetSymbolAddress((void**)&H1l, g_H1l);
        cudaGetSymbolAddress((void**)&Wqh, g_Wqh);
        cudaGetSymbolAddress((void**)&Wql, g_Wql);
        cudaGetSymbolAddress((void**)&Wph, g_Wph);
        cudaGetSymbolAddress((void**)&Wpl, g_Wpl);
        cudaGetSymbolAddress((void**)&W1h, g_W1h);
        cudaGetSymbolAddress((void**)&W1l, g_W1l);
        cudaGetSymbolAddress((void**)&W2h, g_W2h);
        cudaGetSymbolAddress((void**)&W2l, g_W2l);
        cudaGetSymbolAddress((void**)&cf,  g_cflat);
        cudaGetSymbolAddress((void**)&cq,  g_cqkv);
        cudaGetSymbolAddress((void**)&ca,  g_catt);
        cudaGetSymbolAddress((void**)&c2,  g_c2);
        cudaGetSymbolAddress((void**)&cmu, g_cmu);
        cudaGetSymbolAddress((void**)&crs, g_crs);
        const int smem = 61440;
        cudaFuncSetAttribute(gemm_bf<0, false, false, 0>,
                             cudaFuncAttributeMaxDynamicSharedMemorySize, smem);
        cudaFuncSetAttribute(gemm_bf<0, true, true, 0>,
                             cudaFuncAttributeMaxDynamicSharedMemorySize, smem);
        cudaFuncSetAttribute(gemm_bf<1, true, false, 1>,
                             cudaFuncAttributeMaxDynamicSharedMemorySize, smem);
        cudaFuncSetAttribute(gemm_bf<0, true, true, 2>,
                             cudaFuncAttributeMaxDynamicSharedMemorySize, smem);
    }

    const int TPB  = 256;
    const int SMEM = 61440;

    // ---- Weight split (once per call; cheap) ----
    k_split<<<(3 * C_ * C_ + TPB - 1) / TPB, TPB>>>(qkv_w,  Wqh, Wql, 3 * C_ * C_);
    k_split<<<(C_ * C_ + TPB - 1) / TPB, TPB>>>(proj_w, Wph, Wpl, C_ * C_);
    k_split<<<(HID * C_ + TPB - 1) / TPB, TPB>>>(fc1_w,  W1h, W1l, HID * C_);
    k_split<<<(C_ * HID + TPB - 1) / TPB, TPB>>>(fc2_w,  W2h, W2l, C_ * HID);

    // ---- Stage A: cls MHA (old fp32-input kernels) ----
    k_gather_cls<<<(NWIN * C_ + TPB - 1) / TPB, TPB>>>(cls_tokens);
    ln_stats<<<NWIN / 8, 256>>>(cf, cmu, crs, NWIN);
    gemm_tc<false, false, true><<<dim3(3 * C_ / 64, NWIN / 128), 256>>>(
        cf, qkv_w, nullptr, nullptr, cq, NWIN, 3 * C_, C_, cmu, crs, n0w, n0b);
    attn_kernel<64, false, false><<<B_ * NH, 64>>>(cq, nullptr, ca, nullptr, nullptr);
    gemm_tc<true, true, false><<<dim3(C_ / 64, NWIN / 128), 256>>>(
        ca, proj_w, proj_b, cf, c2, NWIN, C_, C_, nullptr, nullptr, nullptr, nullptr);

    // ---- Stage B: build X ----
    k_buildX<<<(MBIG * C_ + TPB - 1) / TPB, TPB>>>(patch_tokens);

    // ---- Stage C: windowed MHA ----
    ln_stats<<<MBIG / 8, 256>>>(X, MU, RS, MBIG);
    k_ln2bf<<<MBIG * C_ / 4 / TPB, TPB>>>(X, MU, RS, n1w, n1b, LNh, LNl);
    gemm_bf<0, false, false, 0><<<dim3(3 * C_ / 64, MBIG / 128), 256, SMEM>>>(
        LNh, LNl, Wqh, Wql, nullptr, nullptr, QKV, nullptr, nullptr, MBIG, 3 * C_, C_);
    attn_kernel<50, true, true><<<NWIN * NH, 64>>>(QKV, rel_pos, nullptr, ATh, ATl);
    gemm_bf<0, true, true, 0><<<dim3(C_ / 64, MBIG / 128), 256, SMEM>>>(
        ATh, ATl, Wph, Wpl, proj_b, X, TMP, nullptr, nullptr, MBIG, C_, C_);

    // ---- Stage D: MLP ----
    ln_stats<<<MBIG / 8, 256>>>(TMP, MU, RS, MBIG);
    k_ln2bf<<<MBIG * C_ / 4 / TPB, TPB>>>(TMP, MU, RS, n2w, n2b, LNh, LNl);
    gemm_bf<1, true, false, 1><<<dim3(HID / 64, MBIG / 128), 256, SMEM>>>(
        LNh, LNl, W1h, W1l, fc1_b, nullptr, nullptr, H1h, H1l, MBIG, HID, C_);
    gemm_bf<0, true, true, 2><<<dim3(C_ / 64, MBIG / 128), 256, SMEM>>>(
        H1h, H1l, W2h, W2l, fc2_b, TMP, out, nullptr, nullptr, MBIG, C_, HID);
}

// round 7
// speedup vs baseline: 1.2110x; 1.0902x over previous
#include <cuda_runtime.h>
#include <cuda_bf16.h>
#include <math.h>

// ---------------------------------------------------------------------------
// Problem constants
// ---------------------------------------------------------------------------
static constexpr int B_    = 32;
static constexpr int C_    = 256;
static constexpr int WS_   = 7;
static constexpr int NH    = 8;
static constexpr int NW    = 64;
static constexpr int NWIN  = B_ * NW;       // 2048
static constexpr int NTOK  = WS_ * WS_ + 1; // 50
static constexpr int MBIG  = NWIN * NTOK;   // 102400
static constexpr int HID   = 4 * C_;        // 1024

// ---------------------------------------------------------------------------
// Scratch
// ---------------------------------------------------------------------------
__device__ float g_X   [(size_t)MBIG * C_];      // window tokens (residual C)
__device__ float g_TMP [(size_t)MBIG * C_];      // post-attn state (residual D)
__device__ float g_QKV [(size_t)MBIG * 3 * C_];  // qkv fp32 (attention input)
__device__ float g_MU  [MBIG];
__device__ float g_RS  [MBIG];

__device__ __nv_bfloat16 g_LNh [(size_t)MBIG * C_];
__device__ __nv_bfloat16 g_LNl [(size_t)MBIG * C_];
__device__ __nv_bfloat16 g_ATh [(size_t)MBIG * C_];
__device__ __nv_bfloat16 g_ATl [(size_t)MBIG * C_];
__device__ __nv_bfloat16 g_H1h [(size_t)MBIG * HID];
__device__ __nv_bfloat16 g_H1l [(size_t)MBIG * HID];

__device__ __nv_bfloat16 g_Wqh[3 * C_ * C_], g_Wql[3 * C_ * C_];
__device__ __nv_bfloat16 g_Wph[C_ * C_],     g_Wpl[C_ * C_];
__device__ __nv_bfloat16 g_W1h[HID * C_],    g_W1l[HID * C_];
__device__ __nv_bfloat16 g_W2h[C_ * HID],    g_W2l[C_ * HID];

__device__ float g_cflat[(size_t)NWIN * C_];
__device__ float g_cqkv [(size_t)NWIN * 3 * C_];
__device__ float g_catt [(size_t)NWIN * C_];
__device__ float g_c2   [(size_t)NWIN * C_];
__device__ float g_cmu  [NWIN];
__device__ float g_crs  [NWIN];

// ---------------------------------------------------------------------------
// Helpers
// ---------------------------------------------------------------------------
__device__ __forceinline__ void mma16816(float* c, const unsigned* a, const unsigned* b)
{
    asm volatile(
        "mma.sync.aligned.m16n8k16.row.col.f32.bf16.bf16.f32 "
        "{%0,%1,%2,%3},{%4,%5,%6,%7},{%8,%9},{%0,%1,%2,%3};"
        : "+f"(c[0]), "+f"(c[1]), "+f"(c[2]), "+f"(c[3])
        : "r"(a[0]), "r"(a[1]), "r"(a[2]), "r"(a[3]), "r"(b[0]), "r"(b[1]));
}

__device__ __forceinline__ void ldsm_x4(unsigned* r, const void* p)
{
    unsigned s = (unsigned)__cvta_generic_to_shared(p);
    asm volatile("ldmatrix.sync.aligned.m8n8.x4.shared.b16 {%0,%1,%2,%3}, [%4];"
        : "=r"(r[0]), "=r"(r[1]), "=r"(r[2]), "=r"(r[3]) : "r"(s));
}

__device__ __forceinline__ void cpa8(void* dst, const void* src)
{
    unsigned d = (unsigned)__cvta_generic_to_shared(dst);
    asm volatile("cp.async.ca.shared.global [%0], [%1], 8;" :: "r"(d), "l"(src));
}
__device__ __forceinline__ void cpa_commit() { asm volatile("cp.async.commit_group;"); }

__device__ __forceinline__ void split2(float v, __nv_bfloat16& h, __nv_bfloat16& l)
{
    h = __float2bfloat16(v);
    l = __float2bfloat16(v - __bfloat162float(h));
}

// ---------------------------------------------------------------------------
// LN stats: one warp per row (C=256)
// ---------------------------------------------------------------------------
__global__ void ln_stats(const float* __restrict__ X,
                         float* __restrict__ mu, float* __restrict__ rs, int M)
{
    int row  = blockIdx.x * 8 + (threadIdx.x >> 5);
    int lane = threadIdx.x & 31;
    if (row >= M) return;
    const float4* p = reinterpret_cast<const float4*>(X + (size_t)row * C_);
    float4 v1 = p[lane], v2 = p[lane + 32];
    float s  = v1.x + v1.y + v1.z + v1.w + v2.x + v2.y + v2.z + v2.w;
    float s2 = v1.x*v1.x + v1.y*v1.y + v1.z*v1.z + v1.w*v1.w
             + v2.x*v2.x + v2.y*v2.y + v2.z*v2.z + v2.w*v2.w;
    #pragma unroll
    for (int o = 16; o > 0; o >>= 1) {
        s  += __shfl_xor_sync(0xffffffffu, s,  o);
        s2 += __shfl_xor_sync(0xffffffffu, s2, o);
    }
    if (lane == 0) {
        float m   = s * (1.0f / C_);
        float var = s2 * (1.0f / C_) - m * m;
        mu[row] = m;
        rs[row] = rsqrtf(var + 1e-5f);
    }
}

// LN + split to bf16 hi/lo. 4 elements per thread.
__global__ void k_ln2bf(const float* __restrict__ X,
                        const float* __restrict__ mu, const float* __restrict__ rs,
                        const float* __restrict__ w, const float* __restrict__ b,
                        __nv_bfloat16* __restrict__ hi, __nv_bfloat16* __restrict__ lo)
{
    int idx = blockIdx.x * blockDim.x + threadIdx.x;
    int row = idx >> 6, c = (idx & 63) * 4;
    float4 x  = *reinterpret_cast<const float4*>(X + (size_t)row * C_ + c);
    float4 w4 = *reinterpret_cast<const float4*>(w + c);
    float4 b4 = *reinterpret_cast<const float4*>(b + c);
    float m = mu[row], r = rs[row];
    float y0 = (x.x - m) * r * w4.x + b4.x;
    float y1 = (x.y - m) * r * w4.y + b4.y;
    float y2 = (x.z - m) * r * w4.z + b4.z;
    float y3 = (x.w - m) * r * w4.w + b4.w;
    __nv_bfloat16 h0, h1, h2, h3, l0, l1, l2, l3;
    split2(y0, h0, l0); split2(y1, h1, l1); split2(y2, h2, l2); split2(y3, h3, l3);
    size_t o = (size_t)row * C_ + c;
    *reinterpret_cast<__nv_bfloat162*>(hi + o)     = __nv_bfloat162(h0, h1);
    *reinterpret_cast<__nv_bfloat162*>(hi + o + 2) = __nv_bfloat162(h2, h3);
    *reinterpret_cast<__nv_bfloat162*>(lo + o)     = __nv_bfloat162(l0, l1);
    *reinterpret_cast<__nv_bfloat162*>(lo + o + 2) = __nv_bfloat162(l2, l3);
}

__global__ void k_split(const float* __restrict__ src,
                        __nv_bfloat16* __restrict__ hi, __nv_bfloat16* __restrict__ lo, int n)
{
    int idx = blockIdx.x * blockDim.x + threadIdx.x;
    if (idx >= n) return;
    __nv_bfloat16 h, l;
    split2(src[idx], h, l);
    hi[idx] = h; lo[idx] = l;
}

// ---------------------------------------------------------------------------
// Split-bf16 GEMM v3: cp.async fills + ldmatrix fragment loads + MMA.
// C[M,N] = (Ahi+Alo)[M,K] @ (Whi+Wlo)[N,K]^T, 3-term.
// CTA tile 128x64x32, 2-stage pipeline, 8 warps 4x2, warp tile 32x32.
// OUTM: 0 = fp32, 1 = bf16 hi/lo, 2 = fp32 scatter to output layout.
// ---------------------------------------------------------------------------
template<int ACT, bool HAS_BIAS, bool HAS_RES, int OUTM>
__global__ void __launch_bounds__(256)
gemm_bf(const __nv_bfloat16* __restrict__ Ahi, const __nv_bfloat16* __restrict__ Alo,
        const __nv_bfloat16* __restrict__ Whi, const __nv_bfloat16* __restrict__ Wlo,
        const float* __restrict__ bias, const float* __restrict__ res,
        float* __restrict__ Cout,
        __nv_bfloat16* __restrict__ Ohi, __nv_bfloat16* __restrict__ Olo,
        int M, int N, int K)
{
    constexpr int BM = 128, BN = 64, BK = 32, PAD = 40;
    constexpr int SZA = BM * PAD;
    constexpr int SZB = BN * PAD;
    constexpr int BUFSZ = 2 * SZA + 2 * SZB;   // 15360 shorts
    extern __shared__ unsigned short smu[];

    const int tid  = threadIdx.x;
    const int wrp  = tid >> 5;
    const int lane = tid & 31;
    const int g    = lane >> 2;
    const int q4   = lane & 3;
    const int wm   = (wrp & 3) * 32;
    const int wn   = (wrp >> 2) * 32;
    const int bm   = blockIdx.y * BM;
    const int bn   = blockIdx.x * BN;

    const int r8 = tid >> 3;
    const int f  = tid & 7;

    // ldmatrix lane addressing
    const int sel = lane >> 3;     // matrix index 0..3
    const int ri  = lane & 7;      // row within matrix
    // A: matrices (rows base..+7, c), (base+8.., c), (base.., c+8), (base+8.., c+8)
    const int aRow  = (sel & 1) * 8 + ri;     // + wm + mt*16
    const int aColO = (sel >> 1) * 8;         // + kk*16
    // B: matrices (ntile0, c), (ntile0, c+8), (ntile1, c), (ntile1, c+8)
    const int bRow  = (sel >> 1) * 8 + ri;    // + wn + ntp*16
    const int bColO = (sel & 1) * 8;          // + kk*16

    float acc[2][4][4];
    #pragma unroll
    for (int i = 0; i < 2; i++)
        #pragma unroll
        for (int j = 0; j < 4; j++)
            #pragma unroll
            for (int t = 0; t < 4; t++) acc[i][j][t] = 0.f;

    const int KT = K / BK;

    auto fill = [&](int buf, int kt) {
        unsigned short* Ah = smu + buf * BUFSZ;
        unsigned short* Al = Ah + SZA;
        unsigned short* Bh = Al + SZA;
        unsigned short* Bl = Bh + SZB;
        const size_t koff = (size_t)kt * BK;
        #pragma unroll
        for (int i = 0; i < 4; i++) {
            int r = r8 + i * 32;
            const size_t go = (size_t)(bm + r) * K + koff + f * 4;
            cpa8(&Ah[r * PAD + f * 4], Ahi + go);
            cpa8(&Al[r * PAD + f * 4], Alo + go);
        }
        #pragma unroll
        for (int i = 0; i < 2; i++) {
            int r = r8 + i * 32;
            const size_t go = (size_t)(bn + r) * K + koff + f * 4;
            cpa8(&Bh[r * PAD + f * 4], Whi + go);
            cpa8(&Bl[r * PAD + f * 4], Wlo + go);
        }
    };

    fill(0, 0);
    cpa_commit();

    int buf = 0;
    for (int kt = 0; kt < KT; kt++) {
        if (kt + 1 < KT) {
            fill(buf ^ 1, kt + 1);
            cpa_commit();
            asm volatile("cp.async.wait_group 1;");
        } else {
            asm volatile("cp.async.wait_group 0;");
        }
        __syncthreads();

        unsigned short* Ah = smu + buf * BUFSZ;
        unsigned short* Al = Ah + SZA;
        unsigned short* Bh = Al + SZA;
        unsigned short* Bl = Bh + SZB;

        #pragma unroll
        for (int kk = 0; kk < 2; kk++) {
            const int c0 = kk * 16;
            unsigned a_h[2][4], a_l[2][4], b_h[2][4], b_l[2][4];
            #pragma unroll
            for (int mt = 0; mt < 2; mt++) {
                int r = wm + mt * 16 + aRow;
                ldsm_x4(a_h[mt], &Ah[r * PAD + c0 + aColO]);
                ldsm_x4(a_l[mt], &Al[r * PAD + c0 + aColO]);
            }
            #pragma unroll
            for (int ntp = 0; ntp < 2; ntp++) {
                int r = wn + ntp * 16 + bRow;
                ldsm_x4(b_h[ntp], &Bh[r * PAD + c0 + bColO]);
                ldsm_x4(b_l[ntp], &Bl[r * PAD + c0 + bColO]);
            }
            #pragma unroll
            for (int mt = 0; mt < 2; mt++)
                #pragma unroll
                for (int nt = 0; nt < 4; nt++) {
                    const unsigned* bh = &b_h[nt >> 1][(nt & 1) * 2];
                    const unsigned* bl = &b_l[nt >> 1][(nt & 1) * 2];
                    mma16816(acc[mt][nt], a_h[mt], bh);
                    mma16816(acc[mt][nt], a_h[mt], bl);
                    mma16816(acc[mt][nt], a_l[mt], bh);
                }
        }
        __syncthreads();
        buf ^= 1;
    }

    // Epilogue
    #pragma unroll
    for (int mt = 0; mt < 2; mt++) {
        #pragma unroll
        for (int nt = 0; nt < 4; nt++) {
            int row0 = bm + wm + mt * 16 + g;
            int col0 = bn + wn + nt * 8 + q4 * 2;
            #pragma unroll
            for (int tp = 0; tp < 2; tp++) {
                int row = row0 + tp * 8;
                float v0 = acc[mt][nt][tp * 2 + 0];
                float v1 = acc[mt][nt][tp * 2 + 1];
                if (HAS_BIAS) { v0 += bias[col0]; v1 += bias[col0 + 1]; }
                if (ACT == 1) {
                    v0 = 0.5f * v0 * (1.0f + erff(v0 * 0.70710678118654752f));
                    v1 = 0.5f * v1 * (1.0f + erff(v1 * 0.70710678118654752f));
                }
                if (HAS_RES) {
                    float2 rr = *reinterpret_cast<const float2*>(res + (size_t)row * N + col0);
                    v0 += rr.x; v1 += rr.y;
                }
                if (OUTM == 0) {
                    *reinterpret_cast<float2*>(Cout + (size_t)row * N + col0) =
                        make_float2(v0, v1);
                } else if (OUTM == 1) {
                    __nv_bfloat16 h0, h1, l0, l1;
                    split2(v0, h0, l0); split2(v1, h1, l1);
                    size_t o = (size_t)row * N + col0;
                    *reinterpret_cast<__nv_bfloat162*>(Ohi + o) = __nv_bfloat162(h0, h1);
                    *reinterpret_cast<__nv_bfloat162*>(Olo + o) = __nv_bfloat162(l0, l1);
                } else {
                    int tt = row % NTOK, w = row / NTOK;
                    int b = w >> 6, wi = w & 63;
                    int hk = wi >> 3, wkx = wi & 7;
                    #pragma unroll
                    for (int e = 0; e < 2; e++) {
                        int col = col0 + e;
                        float v = (e == 0) ? v0 : v1;
                        size_t o;
                        if (tt == 0) {
                            o = (((size_t)b * C_ + col) * 8 + hk) * 8 + wkx;
                        } else {
                            int k = tt - 1, ii = k / 7, jj = k % 7;
                            o = (size_t)B_ * C_ * 64 +
                                (((size_t)b * C_ + col) * 56 + hk * 7 + ii) * 56 + wkx * 7 + jj;
                        }
                        Cout[o] = v;
                    }
                }
            }
        }
    }
}

// ---------------------------------------------------------------------------
// Old fp32->split GEMM (cls path only; proven correct)
// ---------------------------------------------------------------------------
__device__ __forceinline__ void cvt4(float4 v, unsigned& h01, unsigned& h23,
                                     unsigned& l01, unsigned& l23)
{
    __nv_bfloat16 h0 = __float2bfloat16(v.x);
    __nv_bfloat16 h1 = __float2bfloat16(v.y);
    __nv_bfloat16 h2 = __float2bfloat16(v.z);
    __nv_bfloat16 h3 = __float2bfloat16(v.w);
    __nv_bfloat16 l0 = __float2bfloat16(v.x - __bfloat162float(h0));
    __nv_bfloat16 l1 = __float2bfloat16(v.y - __bfloat162float(h1));
    __nv_bfloat16 l2 = __float2bfloat16(v.z - __bfloat162float(h2));
    __nv_bfloat16 l3 = __float2bfloat16(v.w - __bfloat162float(h3));
    h01 = (unsigned)__bfloat16_as_ushort(h0) | ((unsigned)__bfloat16_as_ushort(h1) << 16);
    h23 = (unsigned)__bfloat16_as_ushort(h2) | ((unsigned)__bfloat16_as_ushort(h3) << 16);
    l01 = (unsigned)__bfloat16_as_ushort(l0) | ((unsigned)__bfloat16_as_ushort(l1) << 16);
    l23 = (unsigned)__bfloat16_as_ushort(l2) | ((unsigned)__bfloat16_as_ushort(l3) << 16);
}

template<bool HAS_BIAS, bool HAS_RES, bool LNA>
__global__ void __launch_bounds__(256)
gemm_tc(const float* __restrict__ A, const float* __restrict__ W,
        const float* __restrict__ bias, const float* __restrict__ res,
        float* __restrict__ Cout, int M, int N, int K,
        const float* __restrict__ mu, const float* __restrict__ rsg,
        const float* __restrict__ lnw, const float* __restrict__ lnb)
{
    constexpr int BM = 128, BN = 64, BK = 32, PAD = 40;
    __shared__ __align__(16) unsigned short Ah[BM * PAD], Al[BM * PAD];
    __shared__ __align__(16) unsigned short Bh[BN * PAD], Bl[BN * PAD];

    const int tid  = threadIdx.x;
    const int wrp  = tid >> 5;
    const int lane = tid & 31;
    const int g    = lane >> 2;
    const int q4   = lane & 3;
    const int wm   = (wrp & 3) * 32;
    const int wn   = (wrp >> 2) * 32;
    const int bm = blockIdx.y * BM;
    const int bn = blockIdx.x * BN;

    float acc[2][4][4];
    #pragma unroll
    for (int i = 0; i < 2; i++)
        #pragma unroll
        for (int j = 0; j < 4; j++)
            #pragma unroll
            for (int t = 0; t < 4; t++) acc[i][j][t] = 0.f;

    const int KT = K / BK;
    const int f  = tid & 7;

    for (int kt = 0; kt < KT; kt++) {
        #pragma unroll
        for (int i = 0; i < 4; i++) {
            int u = tid + i * 256, r = u >> 3;
            float4 v = *reinterpret_cast<const float4*>(
                A + (size_t)(bm + r) * K + kt * BK + f * 4);
            if (LNA) {
                float m = mu[bm + r], sc = rsg[bm + r];
                float4 w4 = *reinterpret_cast<const float4*>(lnw + kt * BK + f * 4);
                float4 b4 = *reinterpret_cast<const float4*>(lnb + kt * BK + f * 4);
                v.x = (v.x - m) * sc * w4.x + b4.x;
                v.y = (v.y - m) * sc * w4.y + b4.y;
                v.z = (v.z - m) * sc * w4.z + b4.z;
                v.w = (v.w - m) * sc * w4.w + b4.w;
            }
            unsigned h01, h23, l01, l23;
            cvt4(v, h01, h23, l01, l23);
            *reinterpret_cast<uint2*>(&Ah[r * PAD + f * 4]) = make_uint2(h01, h23);
            *reinterpret_cast<uint2*>(&Al[r * PAD + f * 4]) = make_uint2(l01, l23);
        }
        #pragma unroll
        for (int i = 0; i < 2; i++) {
            int u = tid + i * 256, r = u >> 3;
            float4 v = *reinterpret_cast<const float4*>(
                W + (size_t)(bn + r) * K + kt * BK + f * 4);
            unsigned h01, h23, l01, l23;
            cvt4(v, h01, h23, l01, l23);
            *reinterpret_cast<uint2*>(&Bh[r * PAD + f * 4]) = make_uint2(h01, h23);
            *reinterpret_cast<uint2*>(&Bl[r * PAD + f * 4]) = make_uint2(l01, l23);
        }
        __syncthreads();
        #pragma unroll
        for (int kk = 0; kk < 2; kk++) {
            const int c = kk * 16 + q4 * 2;
            unsigned a_h[2][4], a_l[2][4], b_h[4][2], b_l[4][2];
            #pragma unroll
            for (int mt = 0; mt < 2; mt++) {
                int r = wm + mt * 16 + g;
                a_h[mt][0] = *reinterpret_cast<unsigned*>(&Ah[r * PAD + c]);
                a_h[mt][1] = *reinterpret_cast<unsigned*>(&Ah[(r + 8) * PAD + c]);
                a_h[mt][2] = *reinterpret_cast<unsigned*>(&Ah[r * PAD + c + 8]);
                a_h[mt][3] = *reinterpret_cast<unsigned*>(&Ah[(r + 8) * PAD + c + 8]);
                a_l[mt][0] = *reinterpret_cast<unsigned*>(&Al[r * PAD + c]);
                a_l[mt][1] = *reinterpret_cast<unsigned*>(&Al[(r + 8) * PAD + c]);
                a_l[mt][2] = *reinterpret_cast<unsigned*>(&Al[r * PAD + c + 8]);
                a_l[mt][3] = *reinterpret_cast<unsigned*>(&Al[(r + 8) * PAD + c + 8]);
            }
            #pragma unroll
            for (int nt = 0; nt < 4; nt++) {
                int n = wn + nt * 8 + g;
                b_h[nt][0] = *reinterpret_cast<unsigned*>(&Bh[n * PAD + c]);
                b_h[nt][1] = *reinterpret_cast<unsigned*>(&Bh[n * PAD + c + 8]);
                b_l[nt][0] = *reinterpret_cast<unsigned*>(&Bl[n * PAD + c]);
                b_l[nt][1] = *reinterpret_cast<unsigned*>(&Bl[n * PAD + c + 8]);
            }
            #pragma unroll
            for (int mt = 0; mt < 2; mt++)
                #pragma unroll
                for (int nt = 0; nt < 4; nt++) {
                    mma16816(acc[mt][nt], a_h[mt], b_h[nt]);
                    mma16816(acc[mt][nt], a_h[mt], b_l[nt]);
                    mma16816(acc[mt][nt], a_l[mt], b_h[nt]);
                }
        }
        __syncthreads();
    }

    #pragma unroll
    for (int mt = 0; mt < 2; mt++)
        #pragma unroll
        for (int nt = 0; nt < 4; nt++) {
            int row0 = bm + wm + mt * 16 + g;
            int col0 = bn + wn + nt * 8 + q4 * 2;
            #pragma unroll
            for (int t = 0; t < 4; t++) {
                int row = row0 + (t >> 1) * 8;
                int col = col0 + (t & 1);
                float v = acc[mt][nt][t];
                if (HAS_BIAS) v += bias[col];
                if (HAS_RES)  v += res[(size_t)row * N + col];
                Cout[(size_t)row * N + col] = v;
            }
        }
}

// ---------------------------------------------------------------------------
// Attention
// ---------------------------------------------------------------------------
template<int NT, bool BIAS, bool BFOUT>
__global__ void __launch_bounds__(64)
attn_kernel(const float* __restrict__ QKV,
            const float* __restrict__ rel_pos,
            float* __restrict__ OUT,
            __nv_bfloat16* __restrict__ Ohi, __nv_bfloat16* __restrict__ Olo)
{
    int bh = blockIdx.x;
    int w  = bh >> 3;
    int h  = bh & 7;

    __shared__ float qs[NT][32], ks[NT][32], vs[NT][32];
    __shared__ float sc[NT][NT + 3];

    int tid = threadIdx.x;
    const float* base = QKV + (size_t)w * NT * 768 + h * 32;
    for (int idx = tid; idx < NT * 8; idx += 64) {
        int n = idx >> 3, d4 = idx & 7;
        const float4* r = reinterpret_cast<const float4*>(base + (size_t)n * 768 + d4 * 4);
        *reinterpret_cast<float4*>(&qs[n][d4 * 4]) = r[0];
        *reinterpret_cast<float4*>(&ks[n][d4 * 4]) = r[64];
        *reinterpret_cast<float4*>(&vs[n][d4 * 4]) = r[128];
    }
    __syncthreads();

    if (tid < NT) {
        int n = tid;
        float q[32];
        #pragma unroll
        for (int d = 0; d < 32; d++) q[d] = qs[n][d];

        const float scale = 0.17677669529663687f;
        float mx = -1e30f;
        for (int m = 0; m < NT; m++) {
            float s = 0.f;
            #pragma unroll
            for (int d = 0; d < 32; d++) s = fmaf(q[d], ks[m][d], s);
            s *= scale;
            if (BIAS) {
                if (n > 0 && m > 0) {
                    int p = n - 1, qq = m - 1;
                    int ridx = ((p / 7) - (qq / 7) + 6) * 13 + ((p % 7) - (qq % 7) + 6);
                    s += rel_pos[h * 225 + ridx];
                }
            }
            sc[n][m] = s;
            mx = fmaxf(mx, s);
        }
        float sum = 0.f;
        for (int m = 0; m < NT; m++) {
            float e = expf(sc[n][m] - mx);
            sc[n][m] = e;
            sum += e;
        }
        float inv = 1.0f / sum;
        float o[32];
        #pragma unroll
        for (int d = 0; d < 32; d++) o[d] = 0.f;
        for (int m = 0; m < NT; m++) {
            float p = sc[n][m];
            #pragma unroll
            for (int d = 0; d < 32; d++) o[d] = fmaf(p, vs[m][d], o[d]);
        }
        size_t rowoff = (size_t)(w * NT + n) * C_ + h * 32;
        if (BFOUT) {
            #pragma unroll
            for (int d = 0; d < 32; d++) {
                float vv = o[d] * inv;
                __nv_bfloat16 hh, ll;
                split2(vv, hh, ll);
                Ohi[rowoff + d] = hh;
                Olo[rowoff + d] = ll;
            }
        } else {
            #pragma unroll
            for (int d = 0; d < 32; d++) OUT[rowoff + d] = o[d] * inv;
        }
    }
}

// ---------------------------------------------------------------------------
// Data movement
// ---------------------------------------------------------------------------
__global__ void k_gather_cls(const float* __restrict__ cls)
{
    int idx = blockIdx.x * blockDim.x + threadIdx.x;
    if (idx >= NWIN * C_) return;
    int c = idx & 255, row = idx >> 8;
    int b = row >> 6, n = row & 63;
    g_cflat[idx] = cls[((size_t)b * C_ + c) * 64 + n];
}

__global__ void k_buildX(const float* __restrict__ patch)
{
    int idx = blockIdx.x * blockDim.x + threadIdx.x;
    if (idx >= MBIG * C_) return;
    int c = idx & 255, row = idx >> 8;
    int t = row % NTOK, w = row / NTOK;
    if (t == 0) {
        g_X[idx] = g_c2[(size_t)w * C_ + c];
    } else {
        int b = w >> 6, wi = w & 63;
        int hk = wi >> 3, wkx = wi & 7;
        int k = t - 1, i = k / 7, j = k % 7;
        g_X[idx] = patch[(((size_t)b * C_ + c) * 56 + hk * 7 + i) * 56 + wkx * 7 + j];
    }
}

// ---------------------------------------------------------------------------
// Host launcher
// ---------------------------------------------------------------------------
extern "C" void kernel_launch(void* const* d_in, const int* in_sizes, int n_in,
                              void* d_out, int out_size)
{
    (void)in_sizes; (void)n_in; (void)out_size;
    const float* cls_tokens   = (const float*)d_in[0];
    const float* patch_tokens = (const float*)d_in[1];
    const float* n0w = (const float*)d_in[2];
    const float* n0b = (const float*)d_in[3];
    const float* n1w = (const float*)d_in[4];
    const float* n1b = (const float*)d_in[5];
    const float* n2w = (const float*)d_in[6];
    const float* n2b = (const float*)d_in[7];
    const float* qkv_w  = (const float*)d_in[8];
    const float* proj_w = (const float*)d_in[9];
    const float* proj_b = (const float*)d_in[10];
    const float* rel_pos= (const float*)d_in[11];
    const float* fc1_w  = (const float*)d_in[12];
    const float* fc1_b  = (const float*)d_in[13];
    const float* fc2_w  = (const float*)d_in[14];
    const float* fc2_b  = (const float*)d_in[15];
    float* out = (float*)d_out;

    static float *X = nullptr, *TMP, *QKV, *MU, *RS;
    static __nv_bfloat16 *LNh, *LNl, *ATh, *ATl, *H1h, *H1l;
    static __nv_bfloat16 *Wqh, *Wql, *Wph, *Wpl, *W1h, *W1l, *W2h, *W2l;
    static float *cf, *cq, *ca, *c2, *cmu, *crs;
    if (!X) {
        cudaGetSymbolAddress((void**)&X,   g_X);
        cudaGetSymbolAddress((void**)&TMP, g_TMP);
        cudaGetSymbolAddress((void**)&QKV, g_QKV);
        cudaGetSymbolAddress((void**)&MU,  g_MU);
        cudaGetSymbolAddress((void**)&RS,  g_RS);
        cudaGetSymbolAddress((void**)&LNh, g_LNh);
        cudaGetSymbolAddress((void**)&LNl, g_LNl);
        cudaGetSymbolAddress((void**)&ATh, g_ATh);
        cudaGetSymbolAddress((void**)&ATl, g_ATl);
        cudaGetSymbolAddress((void**)&H1h, g_H1h);
        cudaGetSymbolAddress((void**)&H1l, g_H1l);
        cudaGetSymbolAddress((void**)&Wqh, g_Wqh);
        cudaGetSymbolAddress((void**)&Wql, g_Wql);
        cudaGetSymbolAddress((void**)&Wph, g_Wph);
        cudaGetSymbolAddress((void**)&Wpl, g_Wpl);
        cudaGetSymbolAddress((void**)&W1h, g_W1h);
        cudaGetSymbolAddress((void**)&W1l, g_W1l);
        cudaGetSymbolAddress((void**)&W2h, g_W2h);
        cudaGetSymbolAddress((void**)&W2l, g_W2l);
        cudaGetSymbolAddress((void**)&cf,  g_cflat);
        cudaGetSymbolAddress((void**)&cq,  g_cqkv);
        cudaGetSymbolAddress((void**)&ca,  g_catt);
        cudaGetSymbolAddress((void**)&c2,  g_c2);
        cudaGetSymbolAddress((void**)&cmu, g_cmu);
        cudaGetSymbolAddress((void**)&crs, g_crs);
        const int smem = 61440;
        cudaFuncSetAttribute(gemm_bf<0, false, false, 0>,
                             cudaFuncAttributeMaxDynamicSharedMemorySize, smem);
        cudaFuncSetAttribute(gemm_bf<0, true, true, 0>,
                             cudaFuncAttributeMaxDynamicSharedMemorySize, smem);
        cudaFuncSetAttribute(gemm_bf<1, true, false, 1>,
                             cudaFuncAttributeMaxDynamicSharedMemorySize, smem);
        cudaFuncSetAttribute(gemm_bf<0, true, true, 2>,
                             cudaFuncAttributeMaxDynamicSharedMemorySize, smem);
    }

    const int TPB  = 256;
    const int SMEM = 61440;

    // ---- Weight split ----
    k_split<<<(3 * C_ * C_ + TPB - 1) / TPB, TPB>>>(qkv_w,  Wqh, Wql, 3 * C_ * C_);
    k_split<<<(C_ * C_ + TPB - 1) / TPB, TPB>>>(proj_w, Wph, Wpl, C_ * C_);
    k_split<<<(HID * C_ + TPB - 1) / TPB, TPB>>>(fc1_w,  W1h, W1l, HID * C_);
    k_split<<<(C_ * HID + TPB - 1) / TPB, TPB>>>(fc2_w,  W2h, W2l, C_ * HID);

    // ---- Stage A: cls MHA ----
    k_gather_cls<<<(NWIN * C_ + TPB - 1) / TPB, TPB>>>(cls_tokens);
    ln_stats<<<NWIN / 8, 256>>>(cf, cmu, crs, NWIN);
    gemm_tc<false, false, true><<<dim3(3 * C_ / 64, NWIN / 128), 256>>>(
        cf, qkv_w, nullptr, nullptr, cq, NWIN, 3 * C_, C_, cmu, crs, n0w, n0b);
    attn_kernel<64, false, false><<<B_ * NH, 64>>>(cq, nullptr, ca, nullptr, nullptr);
    gemm_tc<true, true, false><<<dim3(C_ / 64, NWIN / 128), 256>>>(
        ca, proj_w, proj_b, cf, c2, NWIN, C_, C_, nullptr, nullptr, nullptr, nullptr);

    // ---- Stage B: build X ----
    k_buildX<<<(MBIG * C_ + TPB - 1) / TPB, TPB>>>(patch_tokens);

    // ---- Stage C: windowed MHA ----
    ln_stats<<<MBIG / 8, 256>>>(X, MU, RS, MBIG);
    k_ln2bf<<<MBIG * C_ / 4 / TPB, TPB>>>(X, MU, RS, n1w, n1b, LNh, LNl);
    gemm_bf<0, false, false, 0><<<dim3(3 * C_ / 64, MBIG / 128), 256, SMEM>>>(
        LNh, LNl, Wqh, Wql, nullptr, nullptr, QKV, nullptr, nullptr, MBIG, 3 * C_, C_);
    attn_kernel<50, true, true><<<NWIN * NH, 64>>>(QKV, rel_pos, nullptr, ATh, ATl);
    gemm_bf<0, true, true, 0><<<dim3(C_ / 64, MBIG / 128), 256, SMEM>>>(
        ATh, ATl, Wph, Wpl, proj_b, X, TMP, nullptr, nullptr, MBIG, C_, C_);

    // ---- Stage D: MLP ----
    ln_stats<<<MBIG / 8, 256>>>(TMP, MU, RS, MBIG);
    k_ln2bf<<<MBIG * C_ / 4 / TPB, TPB>>>(TMP, MU, RS, n2w, n2b, LNh, LNl);
    gemm_bf<1, true, false, 1><<<dim3(HID / 64, MBIG / 128), 256, SMEM>>>(
        LNh, LNl, W1h, W1l, fc1_b, nullptr, nullptr, H1h, H1l, MBIG, HID, C_);
    gemm_bf<0, true, true, 2><<<dim3(C_ / 64, MBIG / 128), 256, SMEM>>>(
        H1h, H1l, W2h, W2l, fc2_b, TMP, out, nullptr, nullptr, MBIG, C_, HID);
}